// round 1
// baseline (speedup 1.0000x reference)
#include <cuda_runtime.h>
#include <math.h>
#include <stdint.h>

#define NTOK 16384
#define DIN  1024
#define DBN  256
#define NQ   8
#define NCODE 1024

// ---- scratch (device globals; no allocation allowed) ----
__device__ float g_h1[NTOK * DIN];        // 64 MB hidden buffer (reused enc/dec)
__device__ float g_res[NTOK * DBN];       // 16 MB residual
__device__ float g_cnorm[NQ * NCODE];     // -0.5*||c||^2
__device__ float g_losspart[NQ * 128];    // per-stage per-block loss partials

__device__ __forceinline__ float gelu_exact(float x) {
    return 0.5f * x * (1.0f + erff(x * 0.70710678118654752f));
}

// ============================================================
// SGEMM: C = act(A @ B + bias)   A[M,K] rm, B[K,N] rm, C[M,N] rm
// 128x128 tile, BK=16, 256 threads, 8x8 microtile.
// M,N multiples of 128; K multiple of 16. (All true here.)
// ============================================================
template <int ACT>
__global__ __launch_bounds__(256) void sgemm_bias(
    const float* __restrict__ A, const float* __restrict__ B,
    const float* __restrict__ bias, float* __restrict__ C,
    int M, int N, int K)
{
    __shared__ float As[16][132];   // transposed A tile, padded for LDS.128 alignment
    __shared__ float Bs[16][128];

    const int tid = threadIdx.x;
    const int tx = tid & 15;
    const int ty = tid >> 4;
    const int bm = blockIdx.y * 128;
    const int bn = blockIdx.x * 128;

    float acc[8][8];
#pragma unroll
    for (int i = 0; i < 8; i++)
#pragma unroll
        for (int j = 0; j < 8; j++) acc[i][j] = 0.f;

    const int ar = tid >> 2;          // 0..63
    const int ac = (tid & 3) << 2;    // 0,4,8,12
    const int br = tid >> 5;          // 0..7
    const int bc = (tid & 31) << 2;   // 0..124

    for (int k0 = 0; k0 < K; k0 += 16) {
#pragma unroll
        for (int it = 0; it < 2; ++it) {
            int row = ar + it * 64;
            float4 v = *(const float4*)(A + (size_t)(bm + row) * K + k0 + ac);
            As[ac + 0][row] = v.x;
            As[ac + 1][row] = v.y;
            As[ac + 2][row] = v.z;
            As[ac + 3][row] = v.w;
        }
#pragma unroll
        for (int it = 0; it < 2; ++it) {
            int row = br + it * 8;
            float4 v = *(const float4*)(B + (size_t)(k0 + row) * N + bn + bc);
            *(float4*)&Bs[row][bc] = v;
        }
        __syncthreads();
#pragma unroll
        for (int k = 0; k < 16; k++) {
            float4 a0 = *(const float4*)&As[k][ty * 8];
            float4 a1 = *(const float4*)&As[k][ty * 8 + 4];
            float4 b0 = *(const float4*)&Bs[k][tx * 8];
            float4 b1 = *(const float4*)&Bs[k][tx * 8 + 4];
            float av[8] = {a0.x, a0.y, a0.z, a0.w, a1.x, a1.y, a1.z, a1.w};
            float bv[8] = {b0.x, b0.y, b0.z, b0.w, b1.x, b1.y, b1.z, b1.w};
#pragma unroll
            for (int i = 0; i < 8; i++)
#pragma unroll
                for (int j = 0; j < 8; j++)
                    acc[i][j] += av[i] * bv[j];
        }
        __syncthreads();
    }

#pragma unroll
    for (int i = 0; i < 8; i++) {
        int row = bm + ty * 8 + i;
#pragma unroll
        for (int j4 = 0; j4 < 2; j4++) {
            int col = bn + tx * 8 + j4 * 4;
            float4 bsv = *(const float4*)(bias + col);
            float4 o;
            o.x = acc[i][j4 * 4 + 0] + bsv.x;
            o.y = acc[i][j4 * 4 + 1] + bsv.y;
            o.z = acc[i][j4 * 4 + 2] + bsv.z;
            o.w = acc[i][j4 * 4 + 3] + bsv.w;
            if (ACT) {
                o.x = gelu_exact(o.x);
                o.y = gelu_exact(o.y);
                o.z = gelu_exact(o.z);
                o.w = gelu_exact(o.w);
            }
            *(float4*)(C + (size_t)row * N + col) = o;
        }
    }
}

// ============================================================
// RVQ stage: for 128 tokens/block, score all 1024 codes
// (score = res . c - 0.5||c||^2), argmax, subtract chosen code,
// accumulate sum of squared new residual (commitment partial).
// ============================================================
__global__ __launch_bounds__(256) void rvq_stage(
    const float* __restrict__ cb,    // [1024, 256]
    const float* __restrict__ cn,    // [1024]  (-0.5||c||^2)
    float* __restrict__ res,         // [NTOK, 256] in/out
    float* __restrict__ idx_out,     // [NTOK] float indices
    float* __restrict__ loss_part)   // [128]
{
    __shared__ float As[16][132];
    __shared__ float Bs[16][132];
    __shared__ float sV[128][17];
    __shared__ int   sI[128][17];
    __shared__ int   fIdx[128];
    __shared__ float red[256];

    const int tid = threadIdx.x;
    const int tx = tid & 15;
    const int ty = tid >> 4;
    const int tokBase = blockIdx.x * 128;

    float bestV[8];
    int   bestI[8];
#pragma unroll
    for (int i = 0; i < 8; i++) { bestV[i] = -INFINITY; bestI[i] = 0; }

    const int ar = tid >> 2;
    const int ac = (tid & 3) << 2;

    for (int ct = 0; ct < NCODE; ct += 128) {
        float acc[8][8];
#pragma unroll
        for (int i = 0; i < 8; i++)
#pragma unroll
            for (int j = 0; j < 8; j++) acc[i][j] = 0.f;

        for (int k0 = 0; k0 < DBN; k0 += 16) {
#pragma unroll
            for (int it = 0; it < 2; ++it) {
                int row = ar + it * 64;
                float4 v = *(const float4*)(res + (size_t)(tokBase + row) * DBN + k0 + ac);
                As[ac + 0][row] = v.x;
                As[ac + 1][row] = v.y;
                As[ac + 2][row] = v.z;
                As[ac + 3][row] = v.w;
            }
#pragma unroll
            for (int it = 0; it < 2; ++it) {
                int row = ar + it * 64;
                float4 v = *(const float4*)(cb + (size_t)(ct + row) * DBN + k0 + ac);
                Bs[ac + 0][row] = v.x;
                Bs[ac + 1][row] = v.y;
                Bs[ac + 2][row] = v.z;
                Bs[ac + 3][row] = v.w;
            }
            __syncthreads();
#pragma unroll
            for (int k = 0; k < 16; k++) {
                float4 a0 = *(const float4*)&As[k][ty * 8];
                float4 a1 = *(const float4*)&As[k][ty * 8 + 4];
                float4 b0 = *(const float4*)&Bs[k][tx * 8];
                float4 b1 = *(const float4*)&Bs[k][tx * 8 + 4];
                float av[8] = {a0.x, a0.y, a0.z, a0.w, a1.x, a1.y, a1.z, a1.w};
                float bv[8] = {b0.x, b0.y, b0.z, b0.w, b1.x, b1.y, b1.z, b1.w};
#pragma unroll
                for (int i = 0; i < 8; i++)
#pragma unroll
                    for (int j = 0; j < 8; j++)
                        acc[i][j] += av[i] * bv[j];
            }
            __syncthreads();
        }

#pragma unroll
        for (int j = 0; j < 8; j++) {
            int code = ct + tx * 8 + j;
            float cadj = cn[code];
#pragma unroll
            for (int i = 0; i < 8; i++) {
                float v = acc[i][j] + cadj;
                if (v > bestV[i]) { bestV[i] = v; bestI[i] = code; }
            }
        }
    }

#pragma unroll
    for (int i = 0; i < 8; i++) {
        sV[ty * 8 + i][tx] = bestV[i];
        sI[ty * 8 + i][tx] = bestI[i];
    }
    __syncthreads();

    if (tid < 128) {
        float bv = sV[tid][0];
        int bi = sI[tid][0];
#pragma unroll
        for (int c = 1; c < 16; c++) {
            float v = sV[tid][c];
            int ii = sI[tid][c];
            if (v > bv || (v == bv && ii < bi)) { bv = v; bi = ii; }
        }
        fIdx[tid] = bi;
        idx_out[tokBase + tid] = (float)bi;
    }
    __syncthreads();

    // subtract chosen code & accumulate squared new residual
    float lsum = 0.f;
    const int d = tid;  // 256 threads == 256 dims
#pragma unroll 4
    for (int t = 0; t < 128; t++) {
        int ci = fIdx[t];
        float q = cb[(size_t)ci * DBN + d];
        size_t off = (size_t)(tokBase + t) * DBN + d;
        float r = res[off] - q;
        res[off] = r;
        lsum += r * r;
    }
    red[tid] = lsum;
    __syncthreads();
    for (int s = 128; s > 0; s >>= 1) {
        if (tid < s) red[tid] += red[tid + s];
        __syncthreads();
    }
    if (tid == 0) loss_part[blockIdx.x] = red[0];
}

// ============================================================
// helpers
// ============================================================
__global__ void cnorm_kernel(const float* __restrict__ cb, float* __restrict__ cn) {
    __shared__ float red[256];
    int code = blockIdx.x;          // 0..8191 global code id
    float v = cb[(size_t)code * DBN + threadIdx.x];
    red[threadIdx.x] = v * v;
    __syncthreads();
    for (int s = 128; s > 0; s >>= 1) {
        if (threadIdx.x < s) red[threadIdx.x] += red[threadIdx.x + s];
        __syncthreads();
    }
    if (threadIdx.x == 0) cn[code] = -0.5f * red[0];
}

__global__ void copy_f4(const float4* __restrict__ src, float4* __restrict__ dst, int n) {
    int i = blockIdx.x * blockDim.x + threadIdx.x;
    if (i < n) dst[i] = src[i];
}

__global__ void sub_f4(const float4* __restrict__ z, const float4* __restrict__ r,
                       float4* __restrict__ q, int n) {
    int i = blockIdx.x * blockDim.x + threadIdx.x;
    if (i < n) {
        float4 a = z[i], b = r[i], o;
        o.x = a.x - b.x; o.y = a.y - b.y; o.z = a.z - b.z; o.w = a.w - b.w;
        q[i] = o;
    }
}

__global__ void commit_kernel(const float* __restrict__ parts, float* __restrict__ out) {
    __shared__ float red[256];
    float s = 0.f;
    for (int i = threadIdx.x; i < NQ * 128; i += 256) s += parts[i];
    red[threadIdx.x] = s;
    __syncthreads();
    for (int st = 128; st > 0; st >>= 1) {
        if (threadIdx.x < st) red[threadIdx.x] += red[threadIdx.x + st];
        __syncthreads();
    }
    if (threadIdx.x == 0)
        out[0] = 0.25f * red[0] / ((float)NQ * (float)NTOK * (float)DBN);
}

// ============================================================
// launch
// ============================================================
extern "C" void kernel_launch(void* const* d_in, const int* in_sizes, int n_in,
                              void* d_out, int out_size) {
    const float* x   = (const float*)d_in[0];
    const float* We1 = (const float*)d_in[1];
    const float* be1 = (const float*)d_in[2];
    const float* We2 = (const float*)d_in[3];
    const float* be2 = (const float*)d_in[4];
    const float* cbs = (const float*)d_in[5];
    const float* Wd1 = (const float*)d_in[6];
    const float* bd1 = (const float*)d_in[7];
    const float* Wd2 = (const float*)d_in[8];
    const float* bd2 = (const float*)d_in[9];

    float* out      = (float*)d_out;
    float* z_out    = out;                       // 16384*256   = 4194304
    float* q_out    = out + 4194304;             // 16384*256
    float* idx_out  = out + 8388608;             // 8*16384     = 131072
    float* rec_out  = out + 8519680;             // 16384*1024  = 16777216
    float* cm_out   = out + 25296896;            // 1

    float *h1, *res, *cn, *lp;
    cudaGetSymbolAddress((void**)&h1, g_h1);
    cudaGetSymbolAddress((void**)&res, g_res);
    cudaGetSymbolAddress((void**)&cn, g_cnorm);
    cudaGetSymbolAddress((void**)&lp, g_losspart);

    // code norms (recomputed every call: deterministic)
    cnorm_kernel<<<NQ * NCODE, 256>>>(cbs, cn);

    dim3 gBig(DIN / 128, NTOK / 128);   // (8,128)
    dim3 gBn(DBN / 128, NTOK / 128);    // (2,128)

    // encoder
    sgemm_bias<1><<<gBig, 256>>>(x, We1, be1, h1, NTOK, DIN, DIN);
    sgemm_bias<0><<<gBn, 256>>>(h1, We2, be2, z_out, NTOK, DBN, DIN);

    // residual init
    int n4 = NTOK * DBN / 4;  // 1048576
    copy_f4<<<n4 / 256, 256>>>((const float4*)z_out, (float4*)res, n4);

    // RVQ stages
    for (int s = 0; s < NQ; s++) {
        rvq_stage<<<NTOK / 128, 256>>>(cbs + (size_t)s * NCODE * DBN,
                                       cn + s * NCODE, res,
                                       idx_out + s * NTOK, lp + s * 128);
    }

    // quantized = z - res_final
    sub_f4<<<n4 / 256, 256>>>((const float4*)z_out, (const float4*)res,
                              (float4*)q_out, n4);

    // decoder
    sgemm_bias<1><<<gBig, 256>>>(q_out, Wd1, bd1, h1, NTOK, DIN, DBN);
    sgemm_bias<0><<<gBig, 256>>>(h1, Wd2, bd2, rec_out, NTOK, DIN, DIN);

    // commitment scalar
    commit_kernel<<<1, 256>>>(lp, cm_out);
}